// round 8
// baseline (speedup 1.0000x reference)
#include <cuda_runtime.h>
#include <cuda_bf16.h>
#include <cstdint>

#define N_NODES 50000
#define HD 128
#define E_MAX 600000

// ---------------- scratch (device globals; no dynamic allocation) ----------
__device__ float g_dis[N_NODES];                 // rsqrt(degree incl. self-loop)
__device__ int   g_cnt[N_NODES];                 // in-degree histogram (edges only)
__device__ int   g_rowptr[N_NODES + 1];          // CSR row pointers
__device__ int   g_cursor[N_NODES];              // fill cursors
__device__ int   g_bsum[256];                    // scan block sums
__device__ int2  g_csr[E_MAX];                   // packed (src, norm) per edge, dst-sorted
__device__ float g_xw[(size_t)N_NODES * HD];     // x @ W^T of current layer
__device__ float g_h1[(size_t)N_NODES * HD];     // layer-1 output
__device__ int   g_is64;                         // 1 if edge_index stored as int64

// ---------------- init + dtype detect (merged) ------------------------------
__global__ void initdetect_kernel(const int* __restrict__ ew, int n) {
    int i = blockIdx.x * blockDim.x + threadIdx.x;
    if (i < n) g_cnt[i] = 0;
    if (blockIdx.x == 0) {
        __shared__ int found;
        if (threadIdx.x == 0) found = 0;
        __syncthreads();
        int f = 0;
        for (int j = threadIdx.x; j < 2048; j += blockDim.x)
            if (ew[2 * j + 1] != 0) f = 1;
        if (f) atomicOr(&found, 1);
        __syncthreads();
        if (threadIdx.x == 0) g_is64 = found ? 0 : 1;
    }
}

__global__ void hist_kernel(const int* __restrict__ ew, int E) {
    int e = blockIdx.x * blockDim.x + threadIdx.x;
    if (e >= E) return;
    int d = g_is64 ? ew[2 * (E + e)] : ew[E + e];
    atomicAdd(&g_cnt[d], 1);
}

// ---- exclusive scan of g_cnt -> g_rowptr (3 kernels); also emits g_dis ----
__global__ void scanA_kernel(int n) {
    __shared__ int sm[256];
    int i = blockIdx.x * 256 + threadIdx.x;
    int v = (i < n) ? g_cnt[i] : 0;
    if (i < n) g_dis[i] = rsqrtf((float)(v + 1));
    sm[threadIdx.x] = v;
    __syncthreads();
    #pragma unroll
    for (int off = 1; off < 256; off <<= 1) {
        int t = (threadIdx.x >= off) ? sm[threadIdx.x - off] : 0;
        __syncthreads();
        sm[threadIdx.x] += t;
        __syncthreads();
    }
    if (i < n) g_rowptr[i] = sm[threadIdx.x] - v;  // exclusive, block-local
    if (threadIdx.x == 255) g_bsum[blockIdx.x] = sm[255];
}

__global__ void scanB_kernel(int nb) {
    __shared__ int sm[256];
    int v = (threadIdx.x < nb) ? g_bsum[threadIdx.x] : 0;
    sm[threadIdx.x] = v;
    __syncthreads();
    #pragma unroll
    for (int off = 1; off < 256; off <<= 1) {
        int t = (threadIdx.x >= off) ? sm[threadIdx.x - off] : 0;
        __syncthreads();
        sm[threadIdx.x] += t;
        __syncthreads();
    }
    if (threadIdx.x < nb) g_bsum[threadIdx.x] = sm[threadIdx.x] - v;  // exclusive
}

__global__ void scanC_kernel(int n, int E) {
    int i = blockIdx.x * 256 + threadIdx.x;
    if (i < n) {
        int rp = g_rowptr[i] + g_bsum[blockIdx.x];
        g_rowptr[i] = rp;
        g_cursor[i] = rp;
    }
    if (i == 0) g_rowptr[n] = E;
}

__global__ void fill_kernel(const int* __restrict__ ew, int E) {
    int e = blockIdx.x * blockDim.x + threadIdx.x;
    if (e >= E) return;
    int s, d;
    if (g_is64) { s = ew[2 * e]; d = ew[2 * (E + e)]; }
    else        { s = ew[e];     d = ew[E + e]; }
    int pos = atomicAdd(&g_cursor[d], 1);
    float nm = g_dis[s] * g_dis[d];
    g_csr[pos] = make_int2(s, __float_as_int(nm));
}

// ---------------- GEMM: XW = X @ W^T (SIMT, packed f32x2) ------------------
// 128x128 tile, 256 threads, 8x8 reg tile; row_off selects the node chunk.
#define GEMM_SMEM_BYTES ((128 * 129 + 128 * 128) * 4)   // ~131.5 KB

__global__ void __launch_bounds__(256, 1)
gcn_gemm(const float* __restrict__ X, const float* __restrict__ W,
         float* __restrict__ XW, int row_off, int nrows)
{
    extern __shared__ float sm[];
    float* Xs = sm;               // [128][129] padded
    float* Wt = sm + 128 * 129;   // Wt[k][c] = W[c][k]

    const int tid  = threadIdx.x;
    const int row0 = row_off + blockIdx.x * 128;

    #pragma unroll
    for (int i = tid; i < 128 * 32; i += 256) {
        int c = i >> 5, kq = i & 31;
        float4 w4 = *((const float4*)W + c * 32 + kq);
        int k = kq << 2;
        Wt[(k + 0) * 128 + c] = w4.x;
        Wt[(k + 1) * 128 + c] = w4.y;
        Wt[(k + 2) * 128 + c] = w4.z;
        Wt[(k + 3) * 128 + c] = w4.w;
    }
    #pragma unroll
    for (int i = tid; i < 128 * 32; i += 256) {
        int r = i >> 5, kq = i & 31;
        int gr = row0 + r;
        float4 v = make_float4(0.f, 0.f, 0.f, 0.f);
        if (gr < nrows) v = *((const float4*)X + (size_t)gr * 32 + kq);
        float* p = &Xs[r * 129 + (kq << 2)];
        p[0] = v.x; p[1] = v.y; p[2] = v.z; p[3] = v.w;
    }
    __syncthreads();

    const int tx = tid & 15;
    const int ty = tid >> 4;
    const int c0 = tx * 8;
    const float* xb = &Xs[(ty * 8) * 129];

    unsigned long long acc[8][4];
    #pragma unroll
    for (int r = 0; r < 8; r++)
        #pragma unroll
        for (int j = 0; j < 4; j++) acc[r][j] = 0ull;

    #pragma unroll 4
    for (int k = 0; k < 128; k++) {
        const ulonglong2* wrow = (const ulonglong2*)&Wt[k * 128 + c0];
        ulonglong2 wa = wrow[0], wb = wrow[1];
        #pragma unroll
        for (int r = 0; r < 8; r++) {
            float xv = xb[r * 129 + k];
            unsigned long long xx;
            asm("mov.b64 %0, {%1, %1};" : "=l"(xx) : "f"(xv));
            asm("fma.rn.f32x2 %0, %1, %2, %0;" : "+l"(acc[r][0]) : "l"(xx), "l"(wa.x));
            asm("fma.rn.f32x2 %0, %1, %2, %0;" : "+l"(acc[r][1]) : "l"(xx), "l"(wa.y));
            asm("fma.rn.f32x2 %0, %1, %2, %0;" : "+l"(acc[r][2]) : "l"(xx), "l"(wb.x));
            asm("fma.rn.f32x2 %0, %1, %2, %0;" : "+l"(acc[r][3]) : "l"(xx), "l"(wb.y));
        }
    }

    #pragma unroll
    for (int r = 0; r < 8; r++) {
        int gr = row0 + ty * 8 + r;
        if (gr >= nrows) break;
        float v[8];
        #pragma unroll
        for (int j = 0; j < 4; j++) {
            float lo, hi;
            asm("mov.b64 {%0, %1}, %2;" : "=f"(lo), "=f"(hi) : "l"(acc[r][j]));
            v[2 * j] = lo; v[2 * j + 1] = hi;
        }
        float4* xwp = (float4*)&XW[(size_t)gr * HD + c0];
        xwp[0] = make_float4(v[0], v[1], v[2], v[3]);
        xwp[1] = make_float4(v[4], v[5], v[6], v[7]);
    }
}

// ---------------- aggregation: out[d] = b + dis[d]^2*xw[d] + sum norm*xw[s] -
// One warp per destination node in [off, off+cnt).
__global__ void __launch_bounds__(256)
aggregate_kernel(const float* __restrict__ bias,
                 const float* __restrict__ xw,
                 float* __restrict__ out, int off, int cnt)
{
    int rel = blockIdx.x * 8 + (threadIdx.x >> 5);
    if (rel >= cnt) return;
    int node = off + rel;
    int lane = threadIdx.x & 31;

    int beg = g_rowptr[node];
    int end = g_rowptr[node + 1];

    float ds = g_dis[node];
    float sc = ds * ds;
    float4 vs = ((const float4*)(xw + (size_t)node * HD))[lane];
    float4 b4 = ((const float4*)bias)[lane];
    float4 acc;
    acc.x = fmaf(sc, vs.x, b4.x);
    acc.y = fmaf(sc, vs.y, b4.y);
    acc.z = fmaf(sc, vs.z, b4.z);
    acc.w = fmaf(sc, vs.w, b4.w);

    int p = beg;
    for (; p + 4 <= end; p += 4) {
        int2 e0 = g_csr[p + 0];
        int2 e1 = g_csr[p + 1];
        int2 e2 = g_csr[p + 2];
        int2 e3 = g_csr[p + 3];
        float4 v0 = ((const float4*)(xw + (size_t)e0.x * HD))[lane];
        float4 v1 = ((const float4*)(xw + (size_t)e1.x * HD))[lane];
        float4 v2 = ((const float4*)(xw + (size_t)e2.x * HD))[lane];
        float4 v3 = ((const float4*)(xw + (size_t)e3.x * HD))[lane];
        float n0 = __int_as_float(e0.y), n1 = __int_as_float(e1.y);
        float n2 = __int_as_float(e2.y), n3 = __int_as_float(e3.y);
        acc.x = fmaf(n0, v0.x, acc.x); acc.y = fmaf(n0, v0.y, acc.y);
        acc.z = fmaf(n0, v0.z, acc.z); acc.w = fmaf(n0, v0.w, acc.w);
        acc.x = fmaf(n1, v1.x, acc.x); acc.y = fmaf(n1, v1.y, acc.y);
        acc.z = fmaf(n1, v1.z, acc.z); acc.w = fmaf(n1, v1.w, acc.w);
        acc.x = fmaf(n2, v2.x, acc.x); acc.y = fmaf(n2, v2.y, acc.y);
        acc.z = fmaf(n2, v2.z, acc.z); acc.w = fmaf(n2, v2.w, acc.w);
        acc.x = fmaf(n3, v3.x, acc.x); acc.y = fmaf(n3, v3.y, acc.y);
        acc.z = fmaf(n3, v3.z, acc.z); acc.w = fmaf(n3, v3.w, acc.w);
    }
    for (; p < end; p++) {
        int2 e = g_csr[p];
        float4 v = ((const float4*)(xw + (size_t)e.x * HD))[lane];
        float nm = __int_as_float(e.y);
        acc.x = fmaf(nm, v.x, acc.x); acc.y = fmaf(nm, v.y, acc.y);
        acc.z = fmaf(nm, v.z, acc.z); acc.w = fmaf(nm, v.w, acc.w);
    }

    ((float4*)(out + (size_t)node * HD))[lane] = acc;
}

// ---------------- launch ----------------------------------------------------
extern "C" void kernel_launch(void* const* d_in, const int* in_sizes, int n_in,
                              void* d_out, int out_size) {
    const float* emb = (const float*)d_in[0];
    const int*   ew  = (const int*)d_in[1];   // width detected on device
    const float* W1  = (const float*)d_in[2];
    const float* b1  = (const float*)d_in[3];
    const float* W2  = (const float*)d_in[4];
    const float* b2  = (const float*)d_in[5];
    float* out = (float*)d_out;

    const int nrows = in_sizes[0] / HD;       // 50000
    const int E     = in_sizes[1] / 2;        // 600000

    float *xw_p, *h1_p;
    cudaGetSymbolAddress((void**)&xw_p, g_xw);
    cudaGetSymbolAddress((void**)&h1_p, g_h1);

    cudaFuncSetAttribute(gcn_gemm, cudaFuncAttributeMaxDynamicSharedMemorySize,
                         GEMM_SMEM_BYTES);

    // Side stream + events (created once on the first, non-captured call).
    static cudaStream_t s_side = nullptr;
    static cudaEvent_t  s_ev0 = nullptr, s_ev1 = nullptr,
                        s_evA = nullptr, s_evG = nullptr;
    if (s_side == nullptr) {
        cudaStreamCreateWithFlags(&s_side, cudaStreamNonBlocking);
        cudaEventCreateWithFlags(&s_ev0, cudaEventDisableTiming);
        cudaEventCreateWithFlags(&s_ev1, cudaEventDisableTiming);
        cudaEventCreateWithFlags(&s_evA, cudaEventDisableTiming);
        cudaEventCreateWithFlags(&s_evG, cudaEventDisableTiming);
    }

    const int nb_nodes = (nrows + 255) / 256;   // 196
    const int nb_edges = (E + 255) / 256;       // 2344
    const int nb_gemm  = (nrows + 127) / 128;   // 391

    // chunk split for the agg1 -> gemm2 pipeline (chunk0 multiple of 128)
    const int H = ((nrows / 2) / 128) * 128;    // 24960
    const int cnt0 = H, cnt1 = nrows - H;       // 24960, 25040
    const int nb_agg0 = (cnt0 + 7) / 8;
    const int nb_agg1c = (cnt1 + 7) / 8;
    const int nb_g2c0 = cnt0 / 128;             // 195
    const int nb_g2c1 = (cnt1 + 127) / 128;     // 196

    // ---- fork: layer-1 GEMM on side stream, CSR build on main stream ----
    cudaEventRecord(s_ev0, 0);
    cudaStreamWaitEvent(s_side, s_ev0, 0);
    gcn_gemm<<<nb_gemm, 256, GEMM_SMEM_BYTES, s_side>>>(emb, W1, xw_p, 0, nrows);
    cudaEventRecord(s_ev1, s_side);

    initdetect_kernel<<<nb_nodes, 256>>>(ew, nrows);
    hist_kernel<<<nb_edges, 256>>>(ew, E);
    scanA_kernel<<<nb_nodes, 256>>>(nrows);
    scanB_kernel<<<1, 256>>>(nb_nodes);
    scanC_kernel<<<nb_nodes, 256>>>(nrows, E);
    fill_kernel<<<nb_edges, 256>>>(ew, E);

    // ---- join, then pipelined agg1 / gemm2 ----
    cudaStreamWaitEvent(0, s_ev1, 0);

    // agg1 chunk 0 (main), then gemm2 chunk 0 (side) overlapping agg1 chunk 1
    aggregate_kernel<<<nb_agg0, 256>>>(b1, xw_p, h1_p, 0, cnt0);
    cudaEventRecord(s_evA, 0);
    cudaStreamWaitEvent(s_side, s_evA, 0);
    gcn_gemm<<<nb_g2c0, 256, GEMM_SMEM_BYTES, s_side>>>(h1_p, W2, xw_p, 0, nrows);
    cudaEventRecord(s_evG, s_side);

    aggregate_kernel<<<nb_agg1c, 256>>>(b1, xw_p, h1_p, H, cnt1);
    gcn_gemm<<<nb_g2c1, 256, GEMM_SMEM_BYTES>>>(h1_p, W2, xw_p, H, nrows);

    // agg2 needs all of xw2 (both gemm2 chunks)
    cudaStreamWaitEvent(0, s_evG, 0);
    aggregate_kernel<<<(nrows + 7) / 8, 256>>>(b2, xw_p, out, 0, nrows);
}

// round 9
// speedup vs baseline: 1.0241x; 1.0241x over previous
#include <cuda_runtime.h>
#include <cuda_fp16.h>
#include <cstdint>

#define N_NODES 50000
#define HD 128
#define E_MAX 600000

// ---------------- scratch (device globals; no dynamic allocation) ----------
__device__ float  g_dis[N_NODES];                 // rsqrt(degree incl. self-loop)
__device__ int    g_cnt[N_NODES];                 // in-degree histogram (edges only)
__device__ int    g_rowptr[N_NODES + 1];          // CSR row pointers
__device__ int    g_cursor[N_NODES];              // fill cursors
__device__ int    g_bsum[256];                    // scan block sums
__device__ int2   g_csr[E_MAX];                   // packed (src, norm), dst-sorted
__device__ float  g_xw[(size_t)N_NODES * HD];     // x @ W^T (fp32, self term + gemm2 in)
__device__ __half g_xwh[(size_t)N_NODES * HD];    // x @ W^T (fp16, neighbor gathers)
__device__ float  g_h1[(size_t)N_NODES * HD];     // layer-1 output
__device__ int    g_is64;                         // 1 if edge_index stored as int64

struct __align__(8) h4 { __half2 a, b; };

// ---------------- init + dtype detect (merged) ------------------------------
__global__ void initdetect_kernel(const int* __restrict__ ew, int n) {
    int i = blockIdx.x * blockDim.x + threadIdx.x;
    if (i < n) g_cnt[i] = 0;
    if (blockIdx.x == 0) {
        __shared__ int found;
        if (threadIdx.x == 0) found = 0;
        __syncthreads();
        int f = 0;
        for (int j = threadIdx.x; j < 2048; j += blockDim.x)
            if (ew[2 * j + 1] != 0) f = 1;
        if (f) atomicOr(&found, 1);
        __syncthreads();
        if (threadIdx.x == 0) g_is64 = found ? 0 : 1;
    }
}

__global__ void hist_kernel(const int* __restrict__ ew, int E) {
    int e = blockIdx.x * blockDim.x + threadIdx.x;
    if (e >= E) return;
    int d = g_is64 ? ew[2 * (E + e)] : ew[E + e];
    atomicAdd(&g_cnt[d], 1);
}

// ---- exclusive scan of g_cnt -> g_rowptr (3 kernels); also emits g_dis ----
__global__ void scanA_kernel(int n) {
    __shared__ int sm[256];
    int i = blockIdx.x * 256 + threadIdx.x;
    int v = (i < n) ? g_cnt[i] : 0;
    if (i < n) g_dis[i] = rsqrtf((float)(v + 1));
    sm[threadIdx.x] = v;
    __syncthreads();
    #pragma unroll
    for (int off = 1; off < 256; off <<= 1) {
        int t = (threadIdx.x >= off) ? sm[threadIdx.x - off] : 0;
        __syncthreads();
        sm[threadIdx.x] += t;
        __syncthreads();
    }
    if (i < n) g_rowptr[i] = sm[threadIdx.x] - v;
    if (threadIdx.x == 255) g_bsum[blockIdx.x] = sm[255];
}

__global__ void scanB_kernel(int nb) {
    __shared__ int sm[256];
    int v = (threadIdx.x < nb) ? g_bsum[threadIdx.x] : 0;
    sm[threadIdx.x] = v;
    __syncthreads();
    #pragma unroll
    for (int off = 1; off < 256; off <<= 1) {
        int t = (threadIdx.x >= off) ? sm[threadIdx.x - off] : 0;
        __syncthreads();
        sm[threadIdx.x] += t;
        __syncthreads();
    }
    if (threadIdx.x < nb) g_bsum[threadIdx.x] = sm[threadIdx.x] - v;
}

__global__ void scanC_kernel(int n, int E) {
    int i = blockIdx.x * 256 + threadIdx.x;
    if (i < n) {
        int rp = g_rowptr[i] + g_bsum[blockIdx.x];
        g_rowptr[i] = rp;
        g_cursor[i] = rp;
    }
    if (i == 0) g_rowptr[n] = E;
}

__global__ void fill_kernel(const int* __restrict__ ew, int E) {
    int e = blockIdx.x * blockDim.x + threadIdx.x;
    if (e >= E) return;
    int s, d;
    if (g_is64) { s = ew[2 * e]; d = ew[2 * (E + e)]; }
    else        { s = ew[e];     d = ew[E + e]; }
    int pos = atomicAdd(&g_cursor[d], 1);
    float nm = g_dis[s] * g_dis[d];
    g_csr[pos] = make_int2(s, __float_as_int(nm));
}

// ---------------- GEMM: XW = X @ W^T (SIMT, packed f32x2) ------------------
// 128x128 tile, 256 threads, 8x8 reg tile. Also emits fp16 copy for gathers.
#define GEMM_SMEM_BYTES ((128 * 129 + 128 * 128) * 4)   // ~131.5 KB

__global__ void __launch_bounds__(256, 1)
gcn_gemm(const float* __restrict__ X, const float* __restrict__ W,
         float* __restrict__ XW, __half* __restrict__ XWH, int nrows)
{
    extern __shared__ float sm[];
    float* Xs = sm;               // [128][129] padded
    float* Wt = sm + 128 * 129;   // Wt[k][c] = W[c][k]

    const int tid  = threadIdx.x;
    const int row0 = blockIdx.x * 128;

    #pragma unroll
    for (int i = tid; i < 128 * 32; i += 256) {
        int c = i >> 5, kq = i & 31;
        float4 w4 = *((const float4*)W + c * 32 + kq);
        int k = kq << 2;
        Wt[(k + 0) * 128 + c] = w4.x;
        Wt[(k + 1) * 128 + c] = w4.y;
        Wt[(k + 2) * 128 + c] = w4.z;
        Wt[(k + 3) * 128 + c] = w4.w;
    }
    #pragma unroll
    for (int i = tid; i < 128 * 32; i += 256) {
        int r = i >> 5, kq = i & 31;
        int gr = row0 + r;
        float4 v = make_float4(0.f, 0.f, 0.f, 0.f);
        if (gr < nrows) v = *((const float4*)X + (size_t)gr * 32 + kq);
        float* p = &Xs[r * 129 + (kq << 2)];
        p[0] = v.x; p[1] = v.y; p[2] = v.z; p[3] = v.w;
    }
    __syncthreads();

    const int tx = tid & 15;
    const int ty = tid >> 4;
    const int c0 = tx * 8;
    const float* xb = &Xs[(ty * 8) * 129];

    unsigned long long acc[8][4];
    #pragma unroll
    for (int r = 0; r < 8; r++)
        #pragma unroll
        for (int j = 0; j < 4; j++) acc[r][j] = 0ull;

    #pragma unroll 4
    for (int k = 0; k < 128; k++) {
        const ulonglong2* wrow = (const ulonglong2*)&Wt[k * 128 + c0];
        ulonglong2 wa = wrow[0], wb = wrow[1];
        #pragma unroll
        for (int r = 0; r < 8; r++) {
            float xv = xb[r * 129 + k];
            unsigned long long xx;
            asm("mov.b64 %0, {%1, %1};" : "=l"(xx) : "f"(xv));
            asm("fma.rn.f32x2 %0, %1, %2, %0;" : "+l"(acc[r][0]) : "l"(xx), "l"(wa.x));
            asm("fma.rn.f32x2 %0, %1, %2, %0;" : "+l"(acc[r][1]) : "l"(xx), "l"(wa.y));
            asm("fma.rn.f32x2 %0, %1, %2, %0;" : "+l"(acc[r][2]) : "l"(xx), "l"(wb.x));
            asm("fma.rn.f32x2 %0, %1, %2, %0;" : "+l"(acc[r][3]) : "l"(xx), "l"(wb.y));
        }
    }

    #pragma unroll
    for (int r = 0; r < 8; r++) {
        int gr = row0 + ty * 8 + r;
        if (gr >= nrows) break;
        float v[8];
        #pragma unroll
        for (int j = 0; j < 4; j++) {
            float lo, hi;
            asm("mov.b64 {%0, %1}, %2;" : "=f"(lo), "=f"(hi) : "l"(acc[r][j]));
            v[2 * j] = lo; v[2 * j + 1] = hi;
        }
        float4* xwp = (float4*)&XW[(size_t)gr * HD + c0];
        xwp[0] = make_float4(v[0], v[1], v[2], v[3]);
        xwp[1] = make_float4(v[4], v[5], v[6], v[7]);
        h4* xhp = (h4*)&XWH[(size_t)gr * HD + c0];
        h4 h0, h1;
        h0.a = __floats2half2_rn(v[0], v[1]);
        h0.b = __floats2half2_rn(v[2], v[3]);
        h1.a = __floats2half2_rn(v[4], v[5]);
        h1.b = __floats2half2_rn(v[6], v[7]);
        xhp[0] = h0; xhp[1] = h1;
    }
}

// ---------------- aggregation ------------------------------------------------
// out[d] = b + dis[d]^2 * xw[d] + sum norm_e * xwh[src_e]   (gathers in fp16)
__global__ void __launch_bounds__(256)
aggregate_kernel(const float* __restrict__ bias,
                 const float* __restrict__ xw,
                 const __half* __restrict__ xwh,
                 float* __restrict__ out, int n)
{
    int node = blockIdx.x * 8 + (threadIdx.x >> 5);
    int lane = threadIdx.x & 31;
    if (node >= n) return;

    int beg = g_rowptr[node];
    int end = g_rowptr[node + 1];

    float ds = g_dis[node];
    float sc = ds * ds;
    float4 vs = ((const float4*)(xw + (size_t)node * HD))[lane];
    float4 b4 = ((const float4*)bias)[lane];
    float4 acc;
    acc.x = fmaf(sc, vs.x, b4.x);
    acc.y = fmaf(sc, vs.y, b4.y);
    acc.z = fmaf(sc, vs.z, b4.z);
    acc.w = fmaf(sc, vs.w, b4.w);

    int p = beg;
    for (; p + 4 <= end; p += 4) {
        int2 e0 = g_csr[p + 0];
        int2 e1 = g_csr[p + 1];
        int2 e2 = g_csr[p + 2];
        int2 e3 = g_csr[p + 3];
        h4 h0 = ((const h4*)(xwh + (size_t)e0.x * HD))[lane];
        h4 h1 = ((const h4*)(xwh + (size_t)e1.x * HD))[lane];
        h4 h2 = ((const h4*)(xwh + (size_t)e2.x * HD))[lane];
        h4 h3 = ((const h4*)(xwh + (size_t)e3.x * HD))[lane];
        float n0 = __int_as_float(e0.y), n1 = __int_as_float(e1.y);
        float n2 = __int_as_float(e2.y), n3 = __int_as_float(e3.y);
        float2 a0 = __half22float2(h0.a), b0 = __half22float2(h0.b);
        float2 a1 = __half22float2(h1.a), b1 = __half22float2(h1.b);
        float2 a2 = __half22float2(h2.a), b2 = __half22float2(h2.b);
        float2 a3 = __half22float2(h3.a), b3 = __half22float2(h3.b);
        acc.x = fmaf(n0, a0.x, acc.x); acc.y = fmaf(n0, a0.y, acc.y);
        acc.z = fmaf(n0, b0.x, acc.z); acc.w = fmaf(n0, b0.y, acc.w);
        acc.x = fmaf(n1, a1.x, acc.x); acc.y = fmaf(n1, a1.y, acc.y);
        acc.z = fmaf(n1, b1.x, acc.z); acc.w = fmaf(n1, b1.y, acc.w);
        acc.x = fmaf(n2, a2.x, acc.x); acc.y = fmaf(n2, a2.y, acc.y);
        acc.z = fmaf(n2, b2.x, acc.z); acc.w = fmaf(n2, b2.y, acc.w);
        acc.x = fmaf(n3, a3.x, acc.x); acc.y = fmaf(n3, a3.y, acc.y);
        acc.z = fmaf(n3, b3.x, acc.z); acc.w = fmaf(n3, b3.y, acc.w);
    }
    for (; p < end; p++) {
        int2 e = g_csr[p];
        h4 hv = ((const h4*)(xwh + (size_t)e.x * HD))[lane];
        float nm = __int_as_float(e.y);
        float2 fa = __half22float2(hv.a), fb = __half22float2(hv.b);
        acc.x = fmaf(nm, fa.x, acc.x); acc.y = fmaf(nm, fa.y, acc.y);
        acc.z = fmaf(nm, fb.x, acc.z); acc.w = fmaf(nm, fb.y, acc.w);
    }

    ((float4*)(out + (size_t)node * HD))[lane] = acc;
}

// ---------------- launch ----------------------------------------------------
extern "C" void kernel_launch(void* const* d_in, const int* in_sizes, int n_in,
                              void* d_out, int out_size) {
    const float* emb = (const float*)d_in[0];
    const int*   ew  = (const int*)d_in[1];   // width detected on device
    const float* W1  = (const float*)d_in[2];
    const float* b1  = (const float*)d_in[3];
    const float* W2  = (const float*)d_in[4];
    const float* b2  = (const float*)d_in[5];
    float* out = (float*)d_out;

    const int nrows = in_sizes[0] / HD;       // 50000
    const int E     = in_sizes[1] / 2;        // 600000

    float *xw_p, *h1_p;
    __half* xwh_p;
    cudaGetSymbolAddress((void**)&xw_p,  g_xw);
    cudaGetSymbolAddress((void**)&xwh_p, g_xwh);
    cudaGetSymbolAddress((void**)&h1_p,  g_h1);

    cudaFuncSetAttribute(gcn_gemm, cudaFuncAttributeMaxDynamicSharedMemorySize,
                         GEMM_SMEM_BYTES);

    // Side stream + events (created once on the first, non-captured call).
    static cudaStream_t s_side = nullptr;
    static cudaEvent_t  s_ev0 = nullptr, s_ev1 = nullptr;
    if (s_side == nullptr) {
        cudaStreamCreateWithFlags(&s_side, cudaStreamNonBlocking);
        cudaEventCreateWithFlags(&s_ev0, cudaEventDisableTiming);
        cudaEventCreateWithFlags(&s_ev1, cudaEventDisableTiming);
    }

    const int nb_nodes = (nrows + 255) / 256;   // 196
    const int nb_edges = (E + 255) / 256;       // 2344
    const int nb_gemm  = (nrows + 127) / 128;   // 391
    const int nb_agg   = (nrows + 7) / 8;       // 6250

    // ---- fork: layer-1 GEMM on side stream, CSR build on main stream ----
    cudaEventRecord(s_ev0, 0);
    cudaStreamWaitEvent(s_side, s_ev0, 0);
    gcn_gemm<<<nb_gemm, 256, GEMM_SMEM_BYTES, s_side>>>(emb, W1, xw_p, xwh_p, nrows);
    cudaEventRecord(s_ev1, s_side);

    initdetect_kernel<<<nb_nodes, 256>>>(ew, nrows);
    hist_kernel<<<nb_edges, 256>>>(ew, E);
    scanA_kernel<<<nb_nodes, 256>>>(nrows);
    scanB_kernel<<<1, 256>>>(nb_nodes);
    scanC_kernel<<<nb_nodes, 256>>>(nrows, E);
    fill_kernel<<<nb_edges, 256>>>(ew, E);

    // ---- join, then serial tail ----
    cudaStreamWaitEvent(0, s_ev1, 0);
    aggregate_kernel<<<nb_agg, 256>>>(b1, xw_p, xwh_p, h1_p, nrows);
    gcn_gemm<<<nb_gemm, 256, GEMM_SMEM_BYTES>>>(h1_p, W2, xw_p, xwh_p, nrows);
    aggregate_kernel<<<nb_agg, 256>>>(b2, xw_p, xwh_p, out, nrows);
}